// round 1
// baseline (speedup 1.0000x reference)
#include <cuda_runtime.h>

// SceneEngine: closed-form subset-sum factorization.
// Inputs (metadata order): exist_logprob [256,16,9,2], type_logprob [256,16,9,5],
//                          size_logprob [256,16,9,6], color_logprob [256,16,9,10]
// Output: flattened tuple (all float32):
//   exist_prob      [256,16,9,2]  @ 0       (73728)
//   number_prob     [256,16,9]    @ 73728   (36864)
//   type_prob       [256,16,6]    @ 110592  (24576)
//   norm_type_prob  [256,8,5]     @ 135168  (10240)
//   rule_type_prob  [256]         @ 145408  (256)
//   size_prob       [256,16,7]    @ 145664  (28672)
//   norm_size_prob  [256,8,6]     @ 174336  (12288)
//   rule_size_prob  [256]         @ 186624  (256)
//   color_prob      [256,16,11]   @ 186880  (45056)
//   norm_color_prob [256,8,10]    @ 231936  (20480)
//   rule_color_prob [256]         @ 252416  (256)
// total 252672

constexpr int NB = 256;
constexpr int NK = 16;
constexpr int NS = 9;
constexpr int NPAIR = NB * NK;

constexpr int OFF_EXIST  = 0;
constexpr int OFF_NUM    = 73728;
constexpr int OFF_TYPE   = 110592;
constexpr int OFF_NTYPE  = 135168;
constexpr int OFF_RTYPE  = 145408;
constexpr int OFF_SIZE   = 145664;
constexpr int OFF_NSIZE  = 174336;
constexpr int OFF_RSIZE  = 186624;
constexpr int OFF_COLOR  = 186880;
constexpr int OFF_NCOLOR = 231936;
constexpr int OFF_RCOLOR = 252416;

template <int D>
__device__ __forceinline__ void attr_compute(
    const float* __restrict__ attr,   // base pointer of attr_logprob [NPAIR, 9, D]
    const float e0[NS], const float e1[NS],
    float S0, float invZ,
    int pair, int b, int k,
    float* __restrict__ out,
    int off_prob, int off_norm, int off_rule)
{
    const float* __restrict__ a = attr + (size_t)pair * NS * D;

    float p[D];
#pragma unroll
    for (int d = 0; d < D; d++) p[d] = 1.0f;

#pragma unroll
    for (int s = 0; s < NS; s++) {
#pragma unroll
        for (int d = 0; d < D; d++) {
            p[d] *= fmaf(e1[s], expf(a[s * D + d]), e0[s]);
        }
    }

    float sum = 0.0f;
#pragma unroll
    for (int d = 0; d < D; d++) {
        p[d] = (p[d] - S0) * invZ;
        sum += p[d];
    }
    float nic = fminf(sum, 1.0f);

    // prob_full [NPAIR, D+1]
    float* __restrict__ op = out + off_prob + (size_t)pair * (D + 1);
#pragma unroll
    for (int d = 0; d < D; d++) op[d] = p[d];
    op[D] = 1.0f - nic;

    // norm_prob for k < 8: [NB, 8, D]
    if (k < 8) {
        float inv = 1.0f / sum;
        float* __restrict__ on = out + off_norm + (size_t)(b * 8 + k) * D;
#pragma unroll
        for (int d = 0; d < D; d++) on[d] = p[d] * inv;
    }

    // rule_prob[b] = min over k in [0,8) of nic.
    // Threads of the same b occupy an aligned 16-lane group (pair % 32 == lane).
    float v = (k < 8) ? nic : 3.402823466e+38f;
#pragma unroll
    for (int off = 8; off >= 1; off >>= 1)
        v = fminf(v, __shfl_xor_sync(0xFFFFFFFFu, v, off));
    if (k == 0) out[off_rule + b] = v;
}

__global__ __launch_bounds__(32)
void scene_engine_kernel(const float* __restrict__ exist,
                         const float* __restrict__ typ,
                         const float* __restrict__ siz,
                         const float* __restrict__ col,
                         float* __restrict__ out)
{
    int pair = blockIdx.x * blockDim.x + threadIdx.x;
    if (pair >= NPAIR) return;
    int b = pair / NK;
    int k = pair % NK;

    // ---- exist: exp + output, keep e0/e1 in registers ----
    const float* __restrict__ ex = exist + (size_t)pair * NS * 2;
    float* __restrict__ oex = out + OFF_EXIST + (size_t)pair * NS * 2;
    float e0[NS], e1[NS];
#pragma unroll
    for (int s = 0; s < NS; s++) {
        float x0 = ex[2 * s + 0];
        float x1 = ex[2 * s + 1];
        float p0 = expf(x0);
        float p1 = expf(x1);
        e0[s] = p0; e1[s] = p1;
        oex[2 * s + 0] = p0;
        oex[2 * s + 1] = p1;
    }

    // ---- elementary symmetric polynomial DP:
    //      coeff[c] of Π_s (e0_s + t e1_s) = sum over subsets of size c ----
    float c[NS + 1];
    c[0] = 1.0f;
#pragma unroll
    for (int i = 1; i <= NS; i++) c[i] = 0.0f;
#pragma unroll
    for (int s = 0; s < NS; s++) {
#pragma unroll
        for (int j = NS; j >= 1; j--)
            c[j] = fmaf(c[j], e0[s], c[j - 1] * e1[s]);
        c[0] *= e0[s];
    }

    float Z = 0.0f;
#pragma unroll
    for (int j = 1; j <= NS; j++) Z += c[j];
    float invZ = 1.0f / Z;
    float S0 = c[0];

    // ---- number_prob [NPAIR, 9]: count n corresponds to subset size n+1 ----
    float* __restrict__ onum = out + OFF_NUM + (size_t)pair * NS;
#pragma unroll
    for (int n = 0; n < NS; n++) onum[n] = c[n + 1] * invZ;

    // ---- attributes ----
    attr_compute<5>(typ, e0, e1, S0, invZ, pair, b, k, out, OFF_TYPE, OFF_NTYPE, OFF_RTYPE);
    attr_compute<6>(siz, e0, e1, S0, invZ, pair, b, k, out, OFF_SIZE, OFF_NSIZE, OFF_RSIZE);
    attr_compute<10>(col, e0, e1, S0, invZ, pair, b, k, out, OFF_COLOR, OFF_NCOLOR, OFF_RCOLOR);
}

extern "C" void kernel_launch(void* const* d_in, const int* in_sizes, int n_in,
                              void* d_out, int out_size)
{
    const float* exist = (const float*)d_in[0];
    const float* typ   = (const float*)d_in[1];
    const float* siz   = (const float*)d_in[2];
    const float* col   = (const float*)d_in[3];
    float* out = (float*)d_out;

    // 4096 pairs, 32 threads/block, 128 blocks — spread across SMs (latency-bound).
    scene_engine_kernel<<<NPAIR / 32, 32>>>(exist, typ, siz, col, out);
}

// round 3
// speedup vs baseline: 1.3427x; 1.3427x over previous
#include <cuda_runtime.h>

// SceneEngine: closed-form subset-sum factorization (see R0 analysis).
// exp(sum over subset) factorizes: sum over non-empty subsets of
//   Π_s exp(exist[s, in/out]) = Π_s(e0+e1) - Π_s e0.
// number_prob via elementary symmetric polynomial DP; attr probs fold the
// per-d attr weight into the per-slot factor: Π_s(e0 + e1*exp(a[s,d])) - Π e0.
//
// Parallelization: 2 warps per 32 pairs (warp-granular role split, no
// intra-warp divergence):
//   role 0: exist output, symmetric-poly DP, number, type(5), size(6)
//   role 1: color(10)  (recomputes e0/e1 and Z directly — cheap)
// All exps via __expf (MUFU.EX2): rel err ~1e-6 << 1e-3 gate.

constexpr int NS = 9;

constexpr int OFF_EXIST  = 0;
constexpr int OFF_NUM    = 73728;
constexpr int OFF_TYPE   = 110592;
constexpr int OFF_NTYPE  = 135168;
constexpr int OFF_RTYPE  = 145408;
constexpr int OFF_SIZE   = 145664;
constexpr int OFF_NSIZE  = 174336;
constexpr int OFF_RSIZE  = 186624;
constexpr int OFF_COLOR  = 186880;
constexpr int OFF_NCOLOR = 231936;
constexpr int OFF_RCOLOR = 252416;

#define BIGF 3.402823466e+38f

// Computes attr prob_full/norm for one pair; returns nic (min(sum,1)).
template <int D>
__device__ __forceinline__ float attr_compute(
    const float* __restrict__ attr,
    const float e0[NS], const float e1[NS],
    float S0, float invZ,
    int pair, int b, int k,
    float* __restrict__ out,
    int off_prob, int off_norm)
{
    const float* __restrict__ a = attr + (size_t)pair * NS * D;

    float p[D];
#pragma unroll
    for (int d = 0; d < D; d++) p[d] = 1.0f;

#pragma unroll
    for (int s = 0; s < NS; s++) {
#pragma unroll
        for (int d = 0; d < D; d++) {
            p[d] *= fmaf(e1[s], __expf(a[s * D + d]), e0[s]);
        }
    }

    float sum = 0.0f;
#pragma unroll
    for (int d = 0; d < D; d++) {
        p[d] = (p[d] - S0) * invZ;
        sum += p[d];
    }
    float nic = fminf(sum, 1.0f);

    float* __restrict__ op = out + off_prob + (size_t)pair * (D + 1);
#pragma unroll
    for (int d = 0; d < D; d++) op[d] = p[d];
    op[D] = 1.0f - nic;

    if (k < 8) {
        float inv = 1.0f / sum;
        float* __restrict__ on = out + off_norm + (size_t)(b * 8 + k) * D;
#pragma unroll
        for (int d = 0; d < D; d++) on[d] = p[d] * inv;
    }
    return nic;
}

// 8-lane min within each 16-lane group (k = lane&15; only k<8 carry values).
__device__ __forceinline__ float min8(float v)
{
#pragma unroll
    for (int off = 4; off >= 1; off >>= 1)
        v = fminf(v, __shfl_xor_sync(0xFFFFFFFFu, v, off));
    return v;
}

__global__ __launch_bounds__(64)
void scene_engine_kernel(const float* __restrict__ exist,
                         const float* __restrict__ typ,
                         const float* __restrict__ siz,
                         const float* __restrict__ col,
                         float* __restrict__ out)
{
    int warp = (blockIdx.x * 64 + threadIdx.x) >> 5;
    int lane = threadIdx.x & 31;
    int role = warp & 1;
    int pair = (warp >> 1) * 32 + lane;   // each role-warp pair covers 32 pairs
    int b = pair >> 4;
    int k = pair & 15;

    // ---- e0/e1 (both roles need them) ----
    const float* __restrict__ ex = exist + (size_t)pair * NS * 2;
    float e0[NS], e1[NS];
#pragma unroll
    for (int s = 0; s < NS; s++) {
        e0[s] = __expf(ex[2 * s + 0]);
        e1[s] = __expf(ex[2 * s + 1]);
    }
    float S0 = 1.0f;
#pragma unroll
    for (int s = 0; s < NS; s++) S0 *= e0[s];

    if (role == 0) {
        // exist_prob output
        float* __restrict__ oex = out + OFF_EXIST + (size_t)pair * NS * 2;
#pragma unroll
        for (int s = 0; s < NS; s++) {
            oex[2 * s + 0] = e0[s];
            oex[2 * s + 1] = e1[s];
        }

        // elementary symmetric polynomial DP: c[j] = sum over size-j subsets
        float c[NS + 1];
        c[0] = 1.0f;
#pragma unroll
        for (int i = 1; i <= NS; i++) c[i] = 0.0f;
#pragma unroll
        for (int s = 0; s < NS; s++) {
#pragma unroll
            for (int j = NS; j >= 1; j--)
                c[j] = fmaf(c[j], e0[s], c[j - 1] * e1[s]);
            c[0] *= e0[s];
        }
        float Z = 0.0f;
#pragma unroll
        for (int j = 1; j <= NS; j++) Z += c[j];
        float invZ = 1.0f / Z;

        float* __restrict__ onum = out + OFF_NUM + (size_t)pair * NS;
#pragma unroll
        for (int n = 0; n < NS; n++) onum[n] = c[n + 1] * invZ;

        float nict = attr_compute<5>(typ, e0, e1, S0, invZ, pair, b, k, out, OFF_TYPE, OFF_NTYPE);
        float nics = attr_compute<6>(siz, e0, e1, S0, invZ, pair, b, k, out, OFF_SIZE, OFF_NSIZE);

        float vt = (k < 8) ? nict : BIGF;
        float vs = (k < 8) ? nics : BIGF;
        vt = min8(vt);
        vs = min8(vs);
        if ((lane & 15) == 0) {
            out[OFF_RTYPE + b] = vt;
            out[OFF_RSIZE + b] = vs;
        }
    } else {
        // Z = Π(e0+e1) − Π e0 (no DP needed for color role)
        float Zp = 1.0f;
#pragma unroll
        for (int s = 0; s < NS; s++) Zp *= (e0[s] + e1[s]);
        float invZ = 1.0f / (Zp - S0);

        float nicc = attr_compute<10>(col, e0, e1, S0, invZ, pair, b, k, out, OFF_COLOR, OFF_NCOLOR);

        float vc = (k < 8) ? nicc : BIGF;
        vc = min8(vc);
        if ((lane & 15) == 0) out[OFF_RCOLOR + b] = vc;
    }
}

extern "C" void kernel_launch(void* const* d_in, const int* in_sizes, int n_in,
                              void* d_out, int out_size)
{
    const float* exist = (const float*)d_in[0];
    const float* typ   = (const float*)d_in[1];
    const float* siz   = (const float*)d_in[2];
    const float* col   = (const float*)d_in[3];
    float* out = (float*)d_out;

    // 4096 pairs × 2 role-warps = 8192 threads; 128 blocks × 64.
    scene_engine_kernel<<<128, 64>>>(exist, typ, siz, col, out);
}